// round 11
// baseline (speedup 1.0000x reference)
#include <cuda_runtime.h>
#include <cstdint>
#include <math.h>

// IMLE sampler: out[s,b,n] = 1 iff (logits[b,n] + Gumbel(noise[s,b,n])) is in
// the row's top-k.  S=16, B=128, N=16384, k=32.
//
// v11: split read and write streams (test of read/write-mix turnaround):
//   prep: row sum -> bf16 u-space thresholds (TARGETC 64)
//   zero: dedicated write-only pass (full out buffer)
//   main: READ-ONLY stream (noise + bf16 thresholds, 1 cmp/elem) -> smem
//         candidates -> fast keys -> O(c^2) kth -> exact double-log band
//         recompute -> exact rank (lowest-index ties) -> scatter k ones.
//   fallback (fires ~0.003% of rows): widening rescan inside main.

#define NCOLS    16384
#define NV4      (NCOLS/4)
#define THREADS  256
#define ITERS    (NV4/THREADS)   // 16
#define MAXLROWS 256
#define CAP      1024
#define SURV     512
#define TARGETC  64.0f
#define DELTA    0.05f

__device__ unsigned short g_Ub[(size_t)MAXLROWS * NCOLS];  // bf16 thresholds
__device__ float g_C2[MAXLROWS];

__device__ __forceinline__ unsigned f2k(float f) {
    unsigned b = __float_as_uint(f);
    return b ^ ((unsigned)((int)b >> 31) | 0x80000000u);
}
__device__ __forceinline__ float k2f(unsigned k) {
    unsigned b = (k & 0x80000000u) ? (k ^ 0x80000000u) : ~k;
    return __uint_as_float(b);
}
// float32 log chain, correctly rounded via double (immune to fast-math):
// t1=log(u); t3=log(-t1); p = logit - t3   (matches reference op-by-op)
__device__ __forceinline__ float exact_perturb(float u, float lg) {
    float t1 = (float)log((double)u);
    float t3 = (float)log((double)(-t1));
    return lg + (-t3);
}

// ---------------------------------------------------------------------------
__global__ __launch_bounds__(1024)
void prep_kernel(const float* __restrict__ logits)
{
    __shared__ float red[32];
    __shared__ float s_C2;
    const int row = blockIdx.x, tid = threadIdx.x;
    const int lane = tid & 31, warp = tid >> 5;

    const float4* L4 = reinterpret_cast<const float4*>(logits + (size_t)row * NCOLS);
    float s = 0.f;
    #pragma unroll
    for (int c = 0; c < NV4 / 1024; ++c) {
        float4 l = __ldg(&L4[tid + c * 1024]);
        s += __expf(l.x) + __expf(l.y) + __expf(l.z) + __expf(l.w);
    }
    #pragma unroll
    for (int off = 16; off; off >>= 1) s += __shfl_xor_sync(~0u, s, off);
    if (lane == 0) red[warp] = s;
    __syncthreads();
    if (warp == 0) {
        float t = red[lane];
        #pragma unroll
        for (int off = 16; off; off >>= 1) t += __shfl_xor_sync(~0u, t, off);
        if (lane == 0) { s_C2 = TARGETC / t; g_C2[row] = s_C2; }
    }
    __syncthreads();
    const float MC = -s_C2 * 1.4426950408889634f * 1.01f;   // log2-space coef
    uint2* Ub2 = reinterpret_cast<uint2*>(g_Ub + (size_t)row * NCOLS);
    #pragma unroll
    for (int c = 0; c < NV4 / 1024; ++c) {
        float4 l = __ldg(&L4[tid + c * 1024]);
        float U0 = exp2f(MC * __expf(l.x) - 1e-6f);
        float U1 = exp2f(MC * __expf(l.y) - 1e-6f);
        float U2 = exp2f(MC * __expf(l.z) - 1e-6f);
        float U3 = exp2f(MC * __expf(l.w) - 1e-6f);
        if (!(U0 == U0)) U0 = 0.f;   // NaN -> always candidate
        if (!(U1 == U1)) U1 = 0.f;
        if (!(U2 == U2)) U2 = 0.f;
        if (!(U3 == U3)) U3 = 0.f;
        // truncate toward zero: bf16 <= fp32 -> conservative widening
        unsigned b0 = __float_as_uint(U0) >> 16;
        unsigned b1 = __float_as_uint(U1) >> 16;
        unsigned b2 = __float_as_uint(U2) >> 16;
        unsigned b3 = __float_as_uint(U3) >> 16;
        Ub2[tid + c * 1024] = make_uint2(b0 | (b1 << 16), b2 | (b3 << 16));
    }
}

// ---------------------------------------------------------------------------
// Dedicated write-only zero fill (pure write stream, near-peak write BW)
__global__ __launch_bounds__(256)
void zero_kernel(float4* __restrict__ out, int n4)
{
    const float4 z4 = make_float4(0.f, 0.f, 0.f, 0.f);
    int stride = gridDim.x * 256;
    for (int i = blockIdx.x * 256 + threadIdx.x; i < n4; i += stride)
        __stcs(&out[i], z4);
}

// ---------------------------------------------------------------------------
__device__ __forceinline__ void cand4(float4 u, uint2 Uw, int v,
                                      int* s_cnt, unsigned* s_cu, int* s_ci)
{
    float U0 = __uint_as_float(Uw.x << 16);
    float U1 = __uint_as_float(Uw.x & 0xFFFF0000u);
    float U2 = __uint_as_float(Uw.y << 16);
    float U3 = __uint_as_float(Uw.y & 0xFFFF0000u);
    bool b0 = u.x >= U0, b1 = u.y >= U1, b2 = u.z >= U2, b3 = u.w >= U3;
    if (b0 | b1 | b2 | b3) {                       // rare (~1.5% of float4s)
        if (b0) { int p = atomicAdd(s_cnt, 1); if (p < CAP) { s_cu[p] = __float_as_uint(u.x); s_ci[p] = 4*v+0; } }
        if (b1) { int p = atomicAdd(s_cnt, 1); if (p < CAP) { s_cu[p] = __float_as_uint(u.y); s_ci[p] = 4*v+1; } }
        if (b2) { int p = atomicAdd(s_cnt, 1); if (p < CAP) { s_cu[p] = __float_as_uint(u.z); s_ci[p] = 4*v+2; } }
        if (b3) { int p = atomicAdd(s_cnt, 1); if (p < CAP) { s_cu[p] = __float_as_uint(u.w); s_ci[p] = 4*v+3; } }
    }
}

__global__ __launch_bounds__(THREADS, 6)
void main_kernel(const float* __restrict__ noise,
                 const float* __restrict__ logits,
                 const int* __restrict__ kptr,
                 float* __restrict__ out, int Brows)
{
    __shared__ unsigned s_cu[CAP];      // candidate u bits
    __shared__ int      s_ci[CAP];      // candidate index in row
    __shared__ unsigned s_key[CAP];     // fast perturbed-logit keys
    __shared__ float    e_val[SURV];
    __shared__ int      e_idx[SURV];
    __shared__ int      s_cnt, s_scnt, s_tot;
    __shared__ unsigned s_kth;

    const int row = blockIdx.x, tid = threadIdx.x;
    const int lane = tid & 31, warp = tid >> 5;
    const int lrow = row % Brows;
    const size_t rowoff = (size_t)row * NCOLS;
    const size_t logoff = (size_t)lrow * NCOLS;

    if (tid == 0) { s_cnt = 0; s_scnt = 0; s_kth = 0xFFFFFFFFu; }
    __syncthreads();

    int kk = kptr ? __ldg(kptr) : 32;
    if (kk < 1) kk = 1;
    if (kk > NCOLS) kk = NCOLS;

    // ---- Phase A: READ-ONLY barrier-free stream ----
    {
        const float4* n4 = reinterpret_cast<const float4*>(noise + rowoff);
        const uint2*  t2 = reinterpret_cast<const uint2*>(g_Ub + (size_t)lrow * NCOLS);
        #pragma unroll
        for (int c = 0; c < ITERS / 2; ++c) {
            int v0 = tid + (2*c) * THREADS;
            int v1 = v0 + THREADS;
            float4 u0 = __ldcs(&n4[v0]);
            uint2  U0 = __ldg(&t2[v0]);
            float4 u1 = __ldcs(&n4[v1]);
            uint2  U1 = __ldg(&t2[v1]);
            cand4(u0, U0, v0, &s_cnt, s_cu, s_ci);
            cand4(u1, U1, v1, &s_cnt, s_cu, s_ci);
        }
    }
    __syncthreads();
    int cnt = s_cnt;

    // ---- Fallback: widening rescan (fires ~0.003% of rows) ----
    if (cnt < kk || cnt > CAP) {
        const float INV_LN2 = 1.4426950408889634f;
        float C2 = g_C2[lrow];
        float s = 1.0f, sHi = -1.0f;
        int chosen = 0;
        for (int it = 0; it < 64 && !chosen; ++it) {
            int c = 0;
            for (int v = tid; v < NCOLS; v += THREADS) {
                float t = __log2f(noise[rowoff + v]);
                float g = -C2 * __expf(logits[logoff + v]) * INV_LN2 * s - 1e-6f;
                c += (!(g == g) || t >= g) ? 1 : 0;
            }
            #pragma unroll
            for (int off = 16; off; off >>= 1) c += __shfl_xor_sync(~0u, c, off);
            if (lane == 0) s_key[warp] = (unsigned)c;   // scratch
            __syncthreads();
            if (tid == 0) {
                int tot = 0;
                for (int wg = 0; wg < THREADS / 32; ++wg) tot += (int)s_key[wg];
                s_tot = tot;
            }
            __syncthreads();
            int tot = s_tot;
            if (tot >= kk && (sHi < 0.f || s < sHi)) sHi = s;
            if (tot >= kk && tot <= CAP) chosen = 1;
            else if (tot < kk) s *= 4.0f;
            else s *= 0.70710678f;
            __syncthreads();
        }
        if (!chosen) s = (sHi > 0.f) ? sHi : 1e30f;
        if (tid == 0) s_cnt = 0;
        __syncthreads();
        for (int v = tid; v < NCOLS; v += THREADS) {
            float uu = noise[rowoff + v];
            float t  = __log2f(uu);
            float g  = -C2 * __expf(logits[logoff + v]) * INV_LN2 * s - 1e-6f;
            if (!(g == g) || t >= g) {
                int p = atomicAdd(&s_cnt, 1);
                if (p < CAP) { s_cu[p] = __float_as_uint(uu); s_ci[p] = v; }
            }
        }
        __syncthreads();
        cnt = s_cnt;
        if (cnt > CAP) cnt = CAP;
        if (cnt == 0) return;
    }
    if (cnt > CAP) cnt = CAP;
    if (kk > cnt) kk = cnt;

    // ---- Phase B: fast keys (monotone uint; NaN -> max) ----
    for (int i = tid; i < cnt; i += THREADS) {
        float u  = __uint_as_float(s_cu[i]);
        float lg = __ldg(&logits[logoff + s_ci[i]]);
        float p  = lg - __logf(-__logf(u));
        s_key[i] = (p == p) ? f2k(p) : 0xFFFFFFFFu;
    }
    __syncthreads();

    // ---- Phase C: O(c^2) rank count; kth fast key via atomicMin ----
    for (int i = tid; i < cnt; i += THREADS) {
        unsigned ki = s_key[i];
        int r = 0;
        for (int j = 0; j < cnt; ++j) r += (s_key[j] > ki);
        if (r < kk) atomicMin(&s_kth, ki);
    }
    __syncthreads();

    unsigned kth = s_kth;
    float kf = k2f(kth);
    unsigned cut = (kf == kf && kf < 1e30f && kf > -1e30f)
                   ? f2k(kf - DELTA) : kth;

    // ---- Phase D: band survivors -> exact recompute ----
    for (int i = tid; i < cnt; i += THREADS) {
        if (s_key[i] >= cut) {
            int p = atomicAdd(&s_scnt, 1);
            if (p < SURV) {
                float u  = __uint_as_float(s_cu[i]);
                float lg = __ldg(&logits[logoff + s_ci[i]]);
                e_val[p] = exact_perturb(u, lg);
                e_idx[p] = s_ci[i];
            }
        }
    }
    __syncthreads();
    int sc = s_scnt;
    if (sc > SURV) sc = SURV;

    // ---- Phase E: exact O(sc^2) rank, lowest-index tie-break; scatter ----
    for (int i = tid; i < sc; i += THREADS) {
        float pi = e_val[i];
        int   ii = e_idx[i];
        int r = 0;
        for (int j = 0; j < sc; ++j) {
            float pj = e_val[j];
            r += (pj > pi) || (pj == pi && e_idx[j] < ii);
        }
        if (r < kk) out[rowoff + ii] = 1.0f;
    }
}

// ---------------------------------------------------------------------------
extern "C" void kernel_launch(void* const* d_in, const int* in_sizes, int n_in,
                              void* d_out, int out_size) {
    int iK = -1, iU = -1, iL = -1;
    for (int i = 0; i < n_in; ++i)
        if (in_sizes[i] == 1) iK = i;
    long best = -1;
    for (int i = 0; i < n_in; ++i) {
        if (i == iK) continue;
        if ((long)in_sizes[i] > best) { best = in_sizes[i]; iU = i; }
    }
    for (int i = 0; i < n_in; ++i)
        if (i != iK && i != iU) { iL = i; break; }

    const float* logits = (const float*)d_in[iL];
    const float* noise  = (const float*)d_in[iU];
    const int*   kptr   = (iK >= 0) ? (const int*)d_in[iK] : nullptr;
    float* out = (float*)d_out;

    int rows  = in_sizes[iU] / NCOLS;   // S*B = 2048
    int Brows = in_sizes[iL] / NCOLS;   // B   = 128
    if (Brows > MAXLROWS) Brows = MAXLROWS;
    int n4 = rows * NV4;

    prep_kernel<<<Brows, 1024>>>(logits);
    zero_kernel<<<2368, 256>>>((float4*)out, n4);        // write-only pass
    main_kernel<<<rows, THREADS>>>(noise, logits, kptr, out, Brows);
}

// round 12
// speedup vs baseline: 1.0982x; 1.0982x over previous
#include <cuda_runtime.h>
#include <cstdint>
#include <math.h>

// IMLE sampler: out[s,b,n] = 1 iff (logits[b,n] + Gumbel(noise[s,b,n])) is in
// the row's top-k.  S=16, B=128, N=16384, k=32.
//
// v12: warp-specialized producer/consumer main kernel.
//   Warps 0-3 (stream): claim rows, stream noise + bf16 thresholds + zero
//     fill, push candidates to a double-buffered smem slot. NEVER pause for
//     selection -> DRAM stays busy regardless of CTA phase alignment.
//   Warps 4-7 (tail): per slot: fast keys -> O(c^2) kth -> exact double-log
//     band recompute -> exact rank (lowest-index ties) -> scatter ones.
//   Handoff: volatile shared counters + threadfence_block; named barriers
//   bar.sync 1/2 scoped per 128-thread group.

#define NCOLS    16384
#define NV4      (NCOLS/4)
#define STREAMT  128
#define SITERS   (NV4/STREAMT/2)  // 16 (2 float4 per iter per thread)
#define MAXLROWS 256
#define CAP      768
#define SURV     512
#define TARGETC  64.0f
#define DELTA    0.05f
#define GRIDMAIN 888              // 148 SMs * 6 CTAs

__device__ unsigned short g_Ub[(size_t)MAXLROWS * NCOLS];  // bf16 thresholds
__device__ float g_C2[MAXLROWS];
__device__ int   g_row_ctr;

__device__ __forceinline__ unsigned f2k(float f) {
    unsigned b = __float_as_uint(f);
    return b ^ ((unsigned)((int)b >> 31) | 0x80000000u);
}
__device__ __forceinline__ float k2f(unsigned k) {
    unsigned b = (k & 0x80000000u) ? (k ^ 0x80000000u) : ~k;
    return __uint_as_float(b);
}
// float32 log chain, correctly rounded via double (immune to fast-math)
__device__ __forceinline__ float exact_perturb(float u, float lg) {
    float t1 = (float)log((double)u);
    float t3 = (float)log((double)(-t1));
    return lg + (-t3);
}
#define BAR_STREAM() asm volatile("bar.sync 1, 128;" ::: "memory")
#define BAR_TAIL()   asm volatile("bar.sync 2, 128;" ::: "memory")

// ---------------------------------------------------------------------------
__global__ __launch_bounds__(1024)
void prep_kernel(const float* __restrict__ logits)
{
    __shared__ float red[32];
    __shared__ float s_C2;
    const int row = blockIdx.x, tid = threadIdx.x;
    const int lane = tid & 31, warp = tid >> 5;
    if (row == 0 && tid == 0) g_row_ctr = 0;      // reset for main each replay

    const float4* L4 = reinterpret_cast<const float4*>(logits + (size_t)row * NCOLS);
    float s = 0.f;
    #pragma unroll
    for (int c = 0; c < NV4 / 1024; ++c) {
        float4 l = __ldg(&L4[tid + c * 1024]);
        s += __expf(l.x) + __expf(l.y) + __expf(l.z) + __expf(l.w);
    }
    #pragma unroll
    for (int off = 16; off; off >>= 1) s += __shfl_xor_sync(~0u, s, off);
    if (lane == 0) red[warp] = s;
    __syncthreads();
    if (warp == 0) {
        float t = red[lane];
        #pragma unroll
        for (int off = 16; off; off >>= 1) t += __shfl_xor_sync(~0u, t, off);
        if (lane == 0) { s_C2 = TARGETC / t; g_C2[row] = s_C2; }
    }
    __syncthreads();
    const float MC = -s_C2 * 1.4426950408889634f * 1.01f;
    uint2* Ub2 = reinterpret_cast<uint2*>(g_Ub + (size_t)row * NCOLS);
    #pragma unroll
    for (int c = 0; c < NV4 / 1024; ++c) {
        float4 l = __ldg(&L4[tid + c * 1024]);
        float U0 = exp2f(MC * __expf(l.x) - 1e-6f);
        float U1 = exp2f(MC * __expf(l.y) - 1e-6f);
        float U2 = exp2f(MC * __expf(l.z) - 1e-6f);
        float U3 = exp2f(MC * __expf(l.w) - 1e-6f);
        if (!(U0 == U0)) U0 = 0.f;
        if (!(U1 == U1)) U1 = 0.f;
        if (!(U2 == U2)) U2 = 0.f;
        if (!(U3 == U3)) U3 = 0.f;
        unsigned b0 = __float_as_uint(U0) >> 16;   // truncate-down: conservative
        unsigned b1 = __float_as_uint(U1) >> 16;
        unsigned b2 = __float_as_uint(U2) >> 16;
        unsigned b3 = __float_as_uint(U3) >> 16;
        Ub2[tid + c * 1024] = make_uint2(b0 | (b1 << 16), b2 | (b3 << 16));
    }
}

// ---------------------------------------------------------------------------
__device__ __forceinline__ void cand4(float4 u, uint2 Uw, int v,
                                      int* cnt, unsigned* cu, int* ci)
{
    float U0 = __uint_as_float(Uw.x << 16);
    float U1 = __uint_as_float(Uw.x & 0xFFFF0000u);
    float U2 = __uint_as_float(Uw.y << 16);
    float U3 = __uint_as_float(Uw.y & 0xFFFF0000u);
    bool b0 = u.x >= U0, b1 = u.y >= U1, b2 = u.z >= U2, b3 = u.w >= U3;
    if (b0 | b1 | b2 | b3) {
        if (b0) { int p = atomicAdd(cnt, 1); if (p < CAP) { cu[p] = __float_as_uint(u.x); ci[p] = 4*v+0; } }
        if (b1) { int p = atomicAdd(cnt, 1); if (p < CAP) { cu[p] = __float_as_uint(u.y); ci[p] = 4*v+1; } }
        if (b2) { int p = atomicAdd(cnt, 1); if (p < CAP) { cu[p] = __float_as_uint(u.z); ci[p] = 4*v+2; } }
        if (b3) { int p = atomicAdd(cnt, 1); if (p < CAP) { cu[p] = __float_as_uint(u.w); ci[p] = 4*v+3; } }
    }
}

__global__ __launch_bounds__(256, 6)
void main_kernel(const float* __restrict__ noise,
                 const float* __restrict__ logits,
                 const int* __restrict__ kptr,
                 float* __restrict__ out, int Brows, int nrows)
{
    __shared__ unsigned s_cu[2][CAP];
    __shared__ int      s_ci[2][CAP];
    __shared__ int      s_cnt[2];
    __shared__ int      s_rowid[2];
    __shared__ int      s_prod, s_cons;      // row-completion counters
    __shared__ unsigned s_key[CAP];
    __shared__ float    e_val[SURV];
    __shared__ int      e_idx[SURV];
    __shared__ int      s_scnt, s_fcnt, s_tot;
    __shared__ unsigned s_kth;
    __shared__ int      s_red[4];

    const int tid = threadIdx.x;
    if (tid == 0) { s_prod = 0; s_cons = 0; }
    __syncthreads();

    int kk = kptr ? __ldg(kptr) : 32;
    if (kk < 1) kk = 1;
    if (kk > NCOLS) kk = NCOLS;

    volatile int* vprod = &s_prod;
    volatile int* vcons = &s_cons;

    if (tid < STREAMT) {
        // ================= STREAM GROUP (warps 0-3) =================
        for (int r = 0; ; ++r) {
            int slot = r & 1;
            if (tid == 0) {
                while (*vcons < r - 1) __nanosleep(64);   // slot free?
                int row = atomicAdd(&g_row_ctr, 1);
                s_rowid[slot] = (row < nrows) ? row : -1;
                s_cnt[slot] = 0;
            }
            BAR_STREAM();
            int row = s_rowid[slot];
            if (row < 0) {
                if (tid == 0) { __threadfence_block(); *vprod = r + 1; }
                break;
            }
            const size_t rowoff = (size_t)row * NCOLS;
            const int lrow = row % Brows;
            const float4* n4 = reinterpret_cast<const float4*>(noise + rowoff);
            const uint2*  t2 = reinterpret_cast<const uint2*>(g_Ub + (size_t)lrow * NCOLS);
            float4*       o4 = reinterpret_cast<float4*>(out + rowoff);
            const float4 z4 = make_float4(0.f, 0.f, 0.f, 0.f);
            unsigned* cu = s_cu[slot];
            int*      ci = s_ci[slot];
            int*      pc = &s_cnt[slot];
            #pragma unroll
            for (int c = 0; c < SITERS; ++c) {
                int v0 = tid + (2*c) * STREAMT;
                int v1 = v0 + STREAMT;
                float4 u0 = __ldcs(&n4[v0]);
                uint2  U0 = __ldg(&t2[v0]);
                float4 u1 = __ldcs(&n4[v1]);
                uint2  U1 = __ldg(&t2[v1]);
                __stcs(&o4[v0], z4);
                __stcs(&o4[v1], z4);
                cand4(u0, U0, v0, pc, cu, ci);
                cand4(u1, U1, v1, pc, cu, ci);
            }
            BAR_STREAM();
            if (tid == 0) { __threadfence_block(); *vprod = r + 1; }
        }
    } else {
        // ================= TAIL GROUP (warps 4-7) =================
        const int wt = tid - STREAMT;          // 0..127
        const int lane = wt & 31, twarp = wt >> 5;   // 4 warps
        for (int r = 0; ; ++r) {
            int slot = r & 1;
            if (wt == 0) {
                while (*vprod < r + 1) __nanosleep(64);
                __threadfence_block();
                s_scnt = 0; s_fcnt = 0; s_kth = 0xFFFFFFFFu;
            }
            BAR_TAIL();
            int row = s_rowid[slot];
            if (row < 0) break;
            int cnt = s_cnt[slot];
            const int lrow = row % Brows;
            const size_t rowoff = (size_t)row * NCOLS;
            const size_t logoff = (size_t)lrow * NCOLS;
            unsigned* cu = s_cu[slot];
            int*      ci = s_ci[slot];
            int kr = kk;

            // ---- fallback: widening rescan (fires ~0.003% of rows) ----
            if (cnt < kr || cnt > CAP) {
                const float INV_LN2 = 1.4426950408889634f;
                float C2 = g_C2[lrow];
                float s = 1.0f, sHi = -1.0f;
                int chosen = 0;
                for (int it = 0; it < 64 && !chosen; ++it) {
                    int c = 0;
                    for (int v = wt; v < NCOLS; v += 128) {
                        float t = __log2f(noise[rowoff + v]);
                        float g = -C2 * __expf(logits[logoff + v]) * INV_LN2 * s - 1e-6f;
                        c += (!(g == g) || t >= g) ? 1 : 0;
                    }
                    #pragma unroll
                    for (int off = 16; off; off >>= 1) c += __shfl_xor_sync(~0u, c, off);
                    if (lane == 0) s_red[twarp] = c;
                    BAR_TAIL();
                    if (wt == 0)
                        s_tot = s_red[0] + s_red[1] + s_red[2] + s_red[3];
                    BAR_TAIL();
                    int tot = s_tot;
                    if (tot >= kr && (sHi < 0.f || s < sHi)) sHi = s;
                    if (tot >= kr && tot <= CAP) chosen = 1;
                    else if (tot < kr) s *= 4.0f;
                    else s *= 0.70710678f;
                    BAR_TAIL();
                }
                if (!chosen) s = (sHi > 0.f) ? sHi : 1e30f;
                if (wt == 0) s_fcnt = 0;
                BAR_TAIL();
                for (int v = wt; v < NCOLS; v += 128) {
                    float uu = noise[rowoff + v];
                    float t  = __log2f(uu);
                    float g  = -C2 * __expf(logits[logoff + v]) * INV_LN2 * s - 1e-6f;
                    if (!(g == g) || t >= g) {
                        int p = atomicAdd(&s_fcnt, 1);
                        if (p < CAP) { cu[p] = __float_as_uint(uu); ci[p] = v; }
                    }
                }
                BAR_TAIL();
                cnt = s_fcnt;
                if (cnt > CAP) cnt = CAP;
                if (cnt == 0) {
                    BAR_TAIL();
                    if (wt == 0) { __threadfence_block(); *vcons = r + 1; }
                    continue;
                }
            }
            if (cnt > CAP) cnt = CAP;
            if (kr > cnt) kr = cnt;

            // ---- fast keys ----
            for (int i = wt; i < cnt; i += 128) {
                float u  = __uint_as_float(cu[i]);
                float lg = __ldg(&logits[logoff + ci[i]]);
                float p  = lg - __logf(-__logf(u));
                s_key[i] = (p == p) ? f2k(p) : 0xFFFFFFFFu;
            }
            BAR_TAIL();

            // ---- O(c^2) rank count; kth fast key ----
            for (int i = wt; i < cnt; i += 128) {
                unsigned ki = s_key[i];
                int rr = 0;
                for (int j = 0; j < cnt; ++j) rr += (s_key[j] > ki);
                if (rr < kr) atomicMin(&s_kth, ki);
            }
            BAR_TAIL();

            unsigned kth = s_kth;
            float kf = k2f(kth);
            unsigned cut = (kf == kf && kf < 1e30f && kf > -1e30f)
                           ? f2k(kf - DELTA) : kth;

            // ---- band survivors -> exact recompute ----
            for (int i = wt; i < cnt; i += 128) {
                if (s_key[i] >= cut) {
                    int p = atomicAdd(&s_scnt, 1);
                    if (p < SURV) {
                        float u  = __uint_as_float(cu[i]);
                        float lg = __ldg(&logits[logoff + ci[i]]);
                        e_val[p] = exact_perturb(u, lg);
                        e_idx[p] = ci[i];
                    }
                }
            }
            BAR_TAIL();
            int sc = s_scnt;
            if (sc > SURV) sc = SURV;

            // ---- exact rank, lowest-index tie-break; scatter ones ----
            for (int i = wt; i < sc; i += 128) {
                float pi = e_val[i];
                int   ii = e_idx[i];
                int rr = 0;
                for (int j = 0; j < sc; ++j) {
                    float pj = e_val[j];
                    rr += (pj > pi) || (pj == pi && e_idx[j] < ii);
                }
                if (rr < kr) out[rowoff + ii] = 1.0f;
            }
            BAR_TAIL();
            if (wt == 0) { __threadfence_block(); *vcons = r + 1; }
        }
    }
}

// ---------------------------------------------------------------------------
extern "C" void kernel_launch(void* const* d_in, const int* in_sizes, int n_in,
                              void* d_out, int out_size) {
    int iK = -1, iU = -1, iL = -1;
    for (int i = 0; i < n_in; ++i)
        if (in_sizes[i] == 1) iK = i;
    long best = -1;
    for (int i = 0; i < n_in; ++i) {
        if (i == iK) continue;
        if ((long)in_sizes[i] > best) { best = in_sizes[i]; iU = i; }
    }
    for (int i = 0; i < n_in; ++i)
        if (i != iK && i != iU) { iL = i; break; }

    const float* logits = (const float*)d_in[iL];
    const float* noise  = (const float*)d_in[iU];
    const int*   kptr   = (iK >= 0) ? (const int*)d_in[iK] : nullptr;
    float* out = (float*)d_out;

    int rows  = in_sizes[iU] / NCOLS;   // S*B = 2048
    int Brows = in_sizes[iL] / NCOLS;   // B   = 128
    if (Brows > MAXLROWS) Brows = MAXLROWS;

    prep_kernel<<<Brows, 1024>>>(logits);
    main_kernel<<<GRIDMAIN, 256>>>(noise, logits, kptr, out, Brows, rows);
}